// round 3
// baseline (speedup 1.0000x reference)
#include <cuda_runtime.h>

// Shapes (fixed by the problem)
#define BB 128   // batch
#define TT 96    // time
#define HH 64    // hidden
// gates = 4*HH = 256, input dim = 64, N_ITER = 25

// ---------------- device scratch (static: no runtime allocation) ----------------
__device__ __align__(16) float g_Z[TT * BB * 256];       // Z[t][b][j*4+g], gate-interleaved
__device__ __align__(16) float g_finalH[25 * BB * HH];   // final h of suffix scan i (i=1..25)
__device__ __align__(16) float g_maxPref[BB * HH];       // running max of forward prefix h, steps 0..24
__device__ __align__(16) float g_maxFpref[BB * HH];      // same for reversed-input prefix

__device__ __forceinline__ float sigf(float x) {
    return __fdividef(1.0f, 1.0f + __expf(-x));
}
__device__ __forceinline__ float tanh_f(float x) {
    return __fdividef(2.0f, 1.0f + __expf(-2.0f * x)) - 1.0f;
}

// ---------------- kernel 1: Z[t][b][j*4+g] = bih+bhh + x[b,t,:] @ Wih[g*64+j,:] ----------------
__global__ void z_kernel(const float* __restrict__ x, const float* __restrict__ Wih,
                         const float* __restrict__ bih, const float* __restrict__ bhh) {
    __shared__ float xs[BB * 64];  // 32KB: x[:, t, :]
    const int t = blockIdx.x;
    const int tid = threadIdx.x;  // 256 threads

    for (int i = tid; i < BB * 64; i += 256) {
        int b = i >> 6, k = i & 63;
        xs[i] = x[(b * TT + t) * 64 + k];
    }

    const int j = tid >> 2, g = tid & 3;
    const int wrow = g * 64 + j;  // original gate-row index (i,f,g,o blocks of 64)
    float4 w[16];
    const float4* wp = (const float4*)(Wih + wrow * 64);
#pragma unroll
    for (int m = 0; m < 16; m++) w[m] = wp[m];
    const float bias = bih[wrow] + bhh[wrow];
    __syncthreads();

    for (int b = 0; b < BB; b++) {
        const float4* xv = (const float4*)(xs + b * 64);
        float acc = bias;
#pragma unroll
        for (int m = 0; m < 16; m++) {
            float4 xm = xv[m];
            acc = fmaf(xm.x, w[m].x, acc);
            acc = fmaf(xm.y, w[m].y, acc);
            acc = fmaf(xm.z, w[m].z, acc);
            acc = fmaf(xm.w, w[m].w, acc);
        }
        g_Z[(t * BB + b) * 256 + tid] = acc;  // tid == j*4+g
    }
}

// ---------------- kernel 2: 27 LSTM scans (25 suffix + 2 prefix-with-running-max) ----------------
// CTA = (scan, 16-batch chunk). 216 CTAs, 256 threads.
// Thread (j = tid&63, q = tid>>6) owns gate-column j for 4 batch rows (q*4+r).
// smem: Whh padded [row][68] (conflict-free LDS.128 across lanes), + h[16][64].

extern __shared__ float sdyn[];

#define SMW_STRIDE 68
#define SMEM_FLOATS (256 * SMW_STRIDE + 16 * 64)

// 4 FFMAs per gate-component; r-th batch row accumulator ar, h-vector hr
#define ACC4(ar, hr)                                                            \
    ar.x = fmaf(hr.x, w0.x, ar.x); ar.x = fmaf(hr.y, w0.y, ar.x);               \
    ar.x = fmaf(hr.z, w0.z, ar.x); ar.x = fmaf(hr.w, w0.w, ar.x);               \
    ar.y = fmaf(hr.x, w1.x, ar.y); ar.y = fmaf(hr.y, w1.y, ar.y);               \
    ar.y = fmaf(hr.z, w1.z, ar.y); ar.y = fmaf(hr.w, w1.w, ar.y);               \
    ar.z = fmaf(hr.x, w2.x, ar.z); ar.z = fmaf(hr.y, w2.y, ar.z);               \
    ar.z = fmaf(hr.z, w2.z, ar.z); ar.z = fmaf(hr.w, w2.w, ar.z);               \
    ar.w = fmaf(hr.x, w3.x, ar.w); ar.w = fmaf(hr.y, w3.y, ar.w);               \
    ar.w = fmaf(hr.z, w3.z, ar.w); ar.w = fmaf(hr.w, w3.w, ar.w);

#define GATE(ar, zr, cr, hnr, mr) do {                                          \
    float zi = zr.x + ar.x, zf = zr.y + ar.y, zg = zr.z + ar.z, zo = zr.w + ar.w; \
    float ig = sigf(zi), fg = sigf(zf), gg = tanh_f(zg), og = sigf(zo);         \
    cr = fmaf(fg, cr, ig * gg);                                                 \
    hnr = og * tanh_f(cr);                                                      \
    mr = fmaxf(mr, hnr);                                                       \
} while (0)

__global__ void __launch_bounds__(256, 2) scan_kernel(const float* __restrict__ Whh) {
    float* smW  = sdyn;                       // 256 rows x 68 floats
    float* h_sm = sdyn + 256 * SMW_STRIDE;    // 16 x 64 floats

    const int tid = threadIdx.x;
    const int j = tid & 63, q = tid >> 6;

    // Load Whh into padded smem: smW[row*68 + k] = Whh[row*64 + k]
    for (int idx = tid; idx < 256 * 64; idx += 256) {
        int row = idx >> 6, k = idx & 63;
        smW[row * SMW_STRIDE + k] = Whh[idx];
    }
    ((float4*)h_sm)[tid] = make_float4(0.f, 0.f, 0.f, 0.f);  // zero h state
    __syncthreads();

    // ---- block -> (scan, chunk) mapping, balanced over (bid, bid+148) SM pairs ----
    // Work items: scans 0..24 = suffix i=s+1 (length 95-s), 25 = fwd prefix, 26 = rev prefix.
    // Singles (B in [68,148), 1 CTA/SM): 10 longest scans (s=0..9, L=95..86).
    // Pairs (B, B+148): p<16: (s=10,11) + prefixes (L: 85+25, 84+25);
    //                   p in [16,64): (s=12+k) + (s=24-k)  (sum = 154 each);
    //                   p in [64,68): s=18 with itself.
    const int B = blockIdx.x;
    int s, c;
    if (B >= 68 && B < 148) {
        int r = B - 68; s = r >> 3; c = r & 7;
    } else {
        const int p = (B < 68) ? B : (B - 148);
        const bool second = (B >= 148);
        if (p < 16) {
            s = (second ? 25 : 10) + (p >> 3); c = p & 7;
        } else if (p < 64) {
            int k = (p - 16) >> 3; c = (p - 16) & 7;
            s = second ? (24 - k) : (12 + k);
        } else {
            s = 18; c = (p - 64) * 2 + (second ? 1 : 0);
        }
    }

    int t0, dt, nsteps;
    if (s < 25)       { t0 = s + 1; dt = 1;  nsteps = 95 - s; }  // suffix x[:, s+1:]
    else if (s == 25) { t0 = 0;     dt = 1;  nsteps = 25; }      // forward prefix
    else              { t0 = 95;    dt = -1; nsteps = 25; }      // flipped prefix

    const int bbase = c * 16 + q * 4;

    const float* wb0 = smW + (  0 + j) * SMW_STRIDE;
    const float* wb1 = smW + ( 64 + j) * SMW_STRIDE;
    const float* wb2 = smW + (128 + j) * SMW_STRIDE;
    const float* wb3 = smW + (192 + j) * SMW_STRIDE;
    const float* hb0 = h_sm + (q * 4 + 0) * 64;
    const float* hb1 = h_sm + (q * 4 + 1) * 64;
    const float* hb2 = h_sm + (q * 4 + 2) * 64;
    const float* hb3 = h_sm + (q * 4 + 3) * 64;

    float c0 = 0.f, c1 = 0.f, c2 = 0.f, c3 = 0.f;
    float m0 = -2.f, m1 = -2.f, m2 = -2.f, m3 = -2.f;
    float h0n = 0.f, h1n = 0.f, h2n = 0.f, h3n = 0.f;

    const float4* Zv = (const float4*)g_Z;
    int t = t0;
    for (int p = 0; p < nsteps; ++p, t += dt) {
        // Prefetch input-GEMM contributions (L2-resident), folded in after the K loop.
        const int zb = (t * BB + bbase) * 64 + j;
        float4 z0 = Zv[zb];
        float4 z1 = Zv[zb + 64];
        float4 z2 = Zv[zb + 128];
        float4 z3 = Zv[zb + 192];

        float4 a0 = make_float4(0.f, 0.f, 0.f, 0.f);
        float4 a1 = a0, a2 = a0, a3 = a0;
#pragma unroll
        for (int k4 = 0; k4 < 16; ++k4) {
            float4 w0 = *(const float4*)(wb0 + k4 * 4);
            float4 w1 = *(const float4*)(wb1 + k4 * 4);
            float4 w2 = *(const float4*)(wb2 + k4 * 4);
            float4 w3 = *(const float4*)(wb3 + k4 * 4);
            float4 hv0 = *(const float4*)(hb0 + k4 * 4);
            float4 hv1 = *(const float4*)(hb1 + k4 * 4);
            float4 hv2 = *(const float4*)(hb2 + k4 * 4);
            float4 hv3 = *(const float4*)(hb3 + k4 * 4);
            ACC4(a0, hv0);
            ACC4(a1, hv1);
            ACC4(a2, hv2);
            ACC4(a3, hv3);
        }

        GATE(a0, z0, c0, h0n, m0);
        GATE(a1, z1, c1, h1n, m1);
        GATE(a2, z2, c2, h2n, m2);
        GATE(a3, z3, c3, h3n, m3);

        __syncthreads();  // all reads of old h done
        h_sm[(q * 4 + 0) * 64 + j] = h0n;
        h_sm[(q * 4 + 1) * 64 + j] = h1n;
        h_sm[(q * 4 + 2) * 64 + j] = h2n;
        h_sm[(q * 4 + 3) * 64 + j] = h3n;
        __syncthreads();  // new h visible
    }

    if (s < 25) {
        const int o = (s * BB + bbase) * 64 + j;
        g_finalH[o]       = h0n;
        g_finalH[o + 64]  = h1n;
        g_finalH[o + 128] = h2n;
        g_finalH[o + 192] = h3n;
    } else {
        float* dst = (s == 25) ? g_maxPref : g_maxFpref;
        const int o = bbase * 64 + j;
        dst[o]       = m0;
        dst[o + 64]  = m1;
        dst[o + 128] = m2;
        dst[o + 192] = m3;
    }
}

// ---------------- kernel 3: combine maxima + linear epilogue ----------------
// Hs[b][j2<64]  = max(maxPref[b][j], max_s finalH[s][b][j])
// Hs[b][j2>=64] = max(max_s finalH, maxFpref)
// out[b][n][j2] = Hs[b][j2] * Wlin[n] + blin[n]
__global__ void combine_kernel(const float* __restrict__ Wlin, const float* __restrict__ blin,
                               float* __restrict__ out) {
    const int b = blockIdx.x;
    const int j2 = threadIdx.x;  // 128
    const int j = j2 & 63;

    float ms = -2.f;
#pragma unroll
    for (int s = 0; s < 25; s++) ms = fmaxf(ms, g_finalH[(s * BB + b) * 64 + j]);

    const float hval = (j2 < 64) ? fmaxf(g_maxPref[b * 64 + j], ms)
                                 : fmaxf(ms, g_maxFpref[b * 64 + j]);
#pragma unroll
    for (int n = 0; n < 26; n++) {
        out[(b * 26 + n) * 128 + j2] = fmaf(hval, Wlin[n], blin[n]);
    }
}

// ---------------- launch ----------------
extern "C" void kernel_launch(void* const* d_in, const int* in_sizes, int n_in,
                              void* d_out, int out_size) {
    const float* x    = (const float*)d_in[0];
    const float* Wih  = (const float*)d_in[1];
    const float* Whh  = (const float*)d_in[2];
    const float* bih  = (const float*)d_in[3];
    const float* bhh  = (const float*)d_in[4];
    const float* Wlin = (const float*)d_in[5];
    const float* blin = (const float*)d_in[6];
    float* out = (float*)d_out;

    const int smem_bytes = SMEM_FLOATS * (int)sizeof(float);  // 73,728 B
    cudaFuncSetAttribute((const void*)scan_kernel,
                         cudaFuncAttributeMaxDynamicSharedMemorySize, smem_bytes);

    z_kernel<<<TT, 256>>>(x, Wih, bih, bhh);
    scan_kernel<<<216, 256, smem_bytes>>>(Whh);
    combine_kernel<<<BB, 128>>>(Wlin, blin, out);
}